// round 16
// baseline (speedup 1.0000x reference)
#include <cuda_runtime.h>
#include <cstdint>

// Problem shape fixed by setup_inputs(): x = (2, 4, 8, 256, 256) float32.
#define DD   8
#define HH   256
#define WW   256
#define NBC  8
#define HWsz 65536
#define DHWs 524288                  // 2^19
#define HT   4                       // h-rows per block tile
#define NTIL (HH / HT)               // 64
#define NBLOCKS (NBC * 3 * NTIL)     // 1536; edge pairs emit d=0/7 (no copy path)

#define MAX_SHIFT 0.6f
#define BONUS     10.0f

__device__ __forceinline__ float2 f2max(float2 a, float2 b) {
    return make_float2(fmaxf(a.x, b.x), fmaxf(a.y, b.y));
}

__device__ __forceinline__ void cp_async16(unsigned int dst_smem, const void* src) {
    asm volatile("cp.async.cg.shared.global [%0], [%1], 16;"
                 :: "r"(dst_smem), "l"(src) : "memory");
}

// One Newton step. Returns 0 = moved, 1 = converged (valid), 2 = invalid.
__device__ __forceinline__ int quad_step(
    float c000, float pxm, float pxp, float pym, float pyp, float psm, float psp,
    float e011, float e01m, float e0m1, float e0mm,
    float e101, float e10m, float em01, float em0m,
    float e110, float e1m0, float em10, float emm0,
    int& dc, int& hc, int& wc,
    float& shx, float& shy, float& shs, float& gds)
{
    float gx = 0.5f * (pxp - pxm);
    float gy = 0.5f * (pyp - pym);
    float gs = 0.5f * (psp - psm);
    float dxx = pxp - 2.0f * c000 + pxm;
    float dyy = pyp - 2.0f * c000 + pym;
    float dss = psp - 2.0f * c000 + psm;
    float dxy = 0.25f * (e011 - e01m - e0m1 + e0mm);
    float dxs = 0.25f * (e101 - e10m - em01 + em0m);
    float dys = 0.25f * (e110 - e1m0 - em10 + emm0);

    float cf00 = dyy * dss - dys * dys;
    float cf01 = dxy * dss - dys * dxs;
    float cf02 = dxy * dys - dyy * dxs;
    float det  = dxx * cf00 - dxy * cf01 + dxs * cf02;
    if (!(fabsf(det) > 0.0f)) return 2;

    float r0 = -gx, r1 = -gy, r2 = -gs;
    float sx = (r0 * cf00 - dxy * (r1 * dss - dys * r2) + dxs * (r1 * dys - dyy * r2)) / det;
    float sy = (dxx * (r1 * dss - dys * r2) - r0 * cf01 + dxs * (dxy * r2 - r1 * dxs)) / det;
    float ss = (dxx * (dyy * r2 - r1 * dys) - dxy * (dxy * r2 - r1 * dxs) + r0 * cf02) / det;

    shx = sx; shy = sy; shs = ss;
    gds = gx * sx + gy * sy + gs * ss;

    int mvx = (sx > MAX_SHIFT) ? 1 : ((sx < -MAX_SHIFT) ? -1 : 0);
    int nw = wc + mvx;
    if (nw < 1 || nw > WW - 2) return 2;
    wc = nw;
    int mvy = (sy > MAX_SHIFT) ? 1 : ((sy < -MAX_SHIFT) ? -1 : 0);
    int nh = hc + mvy;
    if (nh < 1 || nh > HH - 2) return 2;
    hc = nh;
    int mvs = (ss > MAX_SHIFT) ? 1 : ((ss < -MAX_SHIFT) ? -1 : 0);
    int nd = dc + mvs;
    if (nd < 1 || nd > DD - 2) return 2;
    dc = nd;

    return ((mvx | mvy | mvs) == 0) ? 1 : 0;
}

__global__ __launch_bounds__(128, 7)
void iqi3d_kernel(const float* __restrict__ x, float* __restrict__ out)
{
    const int tid  = threadIdx.x;
    const int lane = tid & 31;
    const int blk  = blockIdx.x;

    const int t    = blk & (NTIL - 1);
    const int q    = blk >> 6;
    const int pair = q % 3;              // 0,1,2  -> masked d = 2p+1, 2p+2
    const int bc   = q / 3;
    const int h0   = t * HT;
    const int dlo  = 2 * pair + 1;
    const int w2   = tid << 1;

    const float* __restrict__ xb = x + (size_t)bc * DHWs;

    // smem: raw input tile [row h0-1..h0+4][plane 2p..2p+3][256 w] = 24 KB
    __shared__ __align__(16) float tilef[6 * 4 * WW];
    __shared__ float sf1[2][WW], sf2[2][WW];
    __shared__ unsigned short slist[512];
    __shared__ int scount;
    if (tid == 0) scount = 0;

    // ---- prologue: async-fill the whole tile (no register destinations) ----
    {
        const unsigned int tbase = (unsigned int)__cvta_generic_to_shared(tilef);
#pragma unroll
        for (int i = 0; i < 12; ++i) {
            const int ch  = i * 128 + tid;      // 0..1535 16B chunks
            const int rp  = ch >> 6;            // 0..23 (row*4 + plane)
            const int w16 = ch & 63;
            const int row = rp >> 2;            // 0..5
            const int pl  = rp & 3;
            int hrow = h0 - 1 + row;
            if (hrow < 0) hrow = 0;
            if (hrow > HH - 1) hrow = HH - 1;
            const float* src = xb + (2 * pair + pl) * HWsz + hrow * WW + (w16 << 2);
            cp_async16(tbase + (unsigned int)(((rp * WW) + (w16 << 2)) << 2), src);
        }
        asm volatile("cp.async.commit_group;" ::: "memory");
        asm volatile("cp.async.wait_group 0;" ::: "memory");
    }
    __syncthreads();

    // ---- init rolling window from the smem tile (tile rows 0,1,2) ----
    float2 M1[3], M2[3], vc[4], vn[4];
#pragma unroll
    for (int rr = 0; rr < 3; ++rr) {
        float2 v0 = *(float2*)&tilef[(rr * 4 + 0) * WW + w2];
        float2 v1 = *(float2*)&tilef[(rr * 4 + 1) * WW + w2];
        float2 v2 = *(float2*)&tilef[(rr * 4 + 2) * WW + w2];
        float2 v3 = *(float2*)&tilef[(rr * 4 + 3) * WW + w2];
        M1[rr] = f2max(f2max(v0, v1), v2);
        M2[rr] = f2max(f2max(v1, v2), v3);
        if (rr == 1) { vc[0] = v0; vc[1] = v1; vc[2] = v2; vc[3] = v3; }
        if (rr == 2) { vn[0] = v0; vn[1] = v1; vn[2] = v2; vn[3] = v3; }
    }

    float* __restrict__ obase = out + (size_t)bc * 3 * DHWs;
    float* __restrict__ ybase = out + (size_t)NBC * 3 * DHWs + (size_t)bc * DHWs;
    const float fw0 = (float)w2, fw1 = (float)(w2 + 1);

#pragma unroll
    for (int r = 0; r < HT; ++r) {
        const int h = h0 + r;

        const float2 full1 = f2max(f2max(M1[0], M1[1]), M1[2]);
        const float2 full2 = f2max(f2max(M2[0], M2[1]), M2[2]);
        const float2 ex1 = f2max(f2max(M1[0], M1[2]), f2max(vc[0], vc[2]));
        const float2 ex2 = f2max(f2max(M2[0], M2[2]), f2max(vc[1], vc[3]));

        const int p = r & 1;
        *(float2*)&sf1[p][w2] = full1;
        *(float2*)&sf2[p][w2] = full2;
        __syncthreads();
        int il = w2 - 1; if (il < 0) il = 0;
        int ir = w2 + 2; if (ir > WW - 1) ir = WW - 1;
        const float fl1 = sf1[p][il], fr1 = sf1[p][ir];
        const float fl2 = sf2[p][il], fr2 = sf2[p][ir];

        const bool hin = (h >= 1) & (h <= HH - 2);
        const bool win0 = (w2 >= 1), win1 = (w2 <= WW - 3);
        const bool mk1x = hin & win0 & (vc[1].x > fmaxf(ex1.x, fmaxf(fl1, full1.y)));
        const bool mk1y = hin & win1 & (vc[1].y > fmaxf(ex1.y, fmaxf(full1.x, fr1)));
        const bool mk2x = hin & win0 & (vc[2].x > fmaxf(ex2.x, fmaxf(fl2, full2.y)));
        const bool mk2y = hin & win1 & (vc[2].y > fmaxf(ex2.y, fmaxf(full2.x, fr2)));

        // warp-aggregated append: one atomic per warp per row
        unsigned b1x = __ballot_sync(0xffffffffu, mk1x);
        unsigned b1y = __ballot_sync(0xffffffffu, mk1y);
        unsigned b2x = __ballot_sync(0xffffffffu, mk2x);
        unsigned b2y = __ballot_sync(0xffffffffu, mk2y);
        if (b1x | b1y | b2x | b2y) {
            int n = __popc(b1x) + __popc(b1y) + __popc(b2x) + __popc(b2y);
            int leader = __ffs(b1x | b1y | b2x | b2y) - 1;
            int base;
            if (lane == leader) base = atomicAdd(&scount, n);
            base = __shfl_sync(0xffffffffu, base, leader);
            unsigned lt = (lane == 31) ? 0x7fffffffu : ((1u << lane) - 1u);
            const int code = (r << 8) | w2;
            int o = base;
            if (mk1x) slist[o + __popc(b1x & lt)] = (unsigned short)code;
            o += __popc(b1x);
            if (mk1y) slist[o + __popc(b1y & lt)] = (unsigned short)(code + 1);
            o += __popc(b1y);
            if (mk2x) slist[o + __popc(b2x & lt)] = (unsigned short)((1 << 11) | code);
            o += __popc(b2x);
            if (mk2y) slist[o + __popc(b2y & lt)] = (unsigned short)((1 << 11) | (code + 1));
        }

        // default outputs for this row
        const float fh = (float)h;
        const int hw = h * WW + w2;
        {
            int off = dlo * HWsz + hw;
            *(float2*)&obase[off]            = make_float2((float)dlo, (float)dlo);
            *(float2*)&obase[DHWs + off]     = make_float2(fw0, fw1);
            *(float2*)&obase[2 * DHWs + off] = make_float2(fh, fh);
            *(float2*)&ybase[off]            = vc[1];
            off += HWsz;
            *(float2*)&obase[off]            = make_float2((float)(dlo + 1), (float)(dlo + 1));
            *(float2*)&obase[DHWs + off]     = make_float2(fw0, fw1);
            *(float2*)&obase[2 * DHWs + off] = make_float2(fh, fh);
            *(float2*)&ybase[off]            = vc[2];
        }
        if (pair == 0) {
            const int off = hw;                       // d = 0
            *(float2*)&obase[off]            = make_float2(0.f, 0.f);
            *(float2*)&obase[DHWs + off]     = make_float2(fw0, fw1);
            *(float2*)&obase[2 * DHWs + off] = make_float2(fh, fh);
            *(float2*)&ybase[off]            = vc[0];
        } else if (pair == 2) {
            const int off = 7 * HWsz + hw;            // d = 7
            *(float2*)&obase[off]            = make_float2(7.f, 7.f);
            *(float2*)&obase[DHWs + off]     = make_float2(fw0, fw1);
            *(float2*)&obase[2 * DHWs + off] = make_float2(fh, fh);
            *(float2*)&ybase[off]            = vc[3];
        }

        // roll: read tile row r+3 from smem (guard: unused past r=2)
        if (r < 3) {
            const int tr = r + 3;
            float2 u0 = *(float2*)&tilef[(tr * 4 + 0) * WW + w2];
            float2 u1 = *(float2*)&tilef[(tr * 4 + 1) * WW + w2];
            float2 u2 = *(float2*)&tilef[(tr * 4 + 2) * WW + w2];
            float2 u3 = *(float2*)&tilef[(tr * 4 + 3) * WW + w2];
            M1[0] = M1[1]; M1[1] = M1[2];
            M2[0] = M2[1]; M2[1] = M2[2];
            M1[2] = f2max(f2max(u0, u1), u2);
            M2[2] = f2max(f2max(u1, u2), u3);
            vc[0] = vn[0]; vc[1] = vn[1]; vc[2] = vn[2]; vc[3] = vn[3];
            vn[0] = u0; vn[1] = u1; vn[2] = u2; vn[3] = u3;
        }
    }

    // =========== phase 2: refine; iteration 0 entirely from the smem tile ===========
    __syncthreads();
    const int cnt = scount;
#pragma unroll 1
    for (int i = tid; i < cnt; i += 128) {
        const int code = slist[i];
        const int dj = (code >> 11) & 1;
        const int r  = (code >> 8) & 3;
        const int w  = code & 255;
        const int d  = dlo + dj;
        const int h  = h0 + r;
        const int sp = d * HWsz + h * WW + w;

        int dc = d, hc = h, wc = w;
        float shx = 0.f, shy = 0.f, shs = 0.f, gds = 0.f;

        // iteration 0 at the original position: all 19 taps from smem.
        const int tb = (((r + 1) * 4) + (dj + 1)) * WW + w;
        #define TT(od, oh, ow) tilef[tb + (oh) * (4 * WW) + (od) * WW + (ow)]
        const float cen = TT(0, 0, 0);
        int st = quad_step(cen,
            TT(0, 0, -1), TT(0, 0, 1),
            TT(0, -1, 0), TT(0, 1, 0),
            TT(-1, 0, 0), TT(1, 0, 0),
            TT(0, 1, 1), TT(0, 1, -1), TT(0, -1, 1), TT(0, -1, -1),
            TT(1, 0, 1), TT(1, 0, -1), TT(-1, 0, 1), TT(-1, 0, -1),
            TT(1, 1, 0), TT(1, -1, 0), TT(-1, 1, 0), TT(-1, -1, 0),
            dc, hc, wc, shx, shy, shs, gds);
        #undef TT

        // iterations 1..4 at (possibly) moved positions: global path
#pragma unroll 1
        for (int itn = 1; (itn < 5) && (st == 0); ++itn) {
            int ds_ = min(max(dc, 1), DD - 2);
            int hs_ = min(max(hc, 1), HH - 2);
            int ws_ = min(max(wc, 1), WW - 2);
            const float* pp = xb + ds_ * HWsz + hs_ * WW + ws_;
            st = quad_step(pp[0],
                pp[-1], pp[1], pp[-WW], pp[WW], pp[-HWsz], pp[HWsz],
                pp[WW + 1], pp[WW - 1], pp[-WW + 1], pp[-WW - 1],
                pp[HWsz + 1], pp[HWsz - 1], pp[-HWsz + 1], pp[-HWsz - 1],
                pp[HWsz + WW], pp[HWsz - WW], pp[-HWsz + WW], pp[-HWsz - WW],
                dc, hc, wc, shx, shy, shs, gds);
        }

        bool valid = (st != 2)
                   && (fabsf(shx) <= 1.5f) && (fabsf(shy) <= 1.5f) && (fabsf(shs) <= 1.5f);
        if (valid) {
            const int cb = bc * 3 * DHWs;
            out[cb + 0 * DHWs + sp] = (float)dc + shs;
            out[cb + 1 * DHWs + sp] = (float)wc + shx;
            out[cb + 2 * DHWs + sp] = (float)hc + shy;
            out[(size_t)NBC * 3 * DHWs + (size_t)bc * DHWs + sp] =
                cen + (0.5f * gds + BONUS);
        }
    }
}

extern "C" void kernel_launch(void* const* d_in, const int* in_sizes, int n_in,
                              void* d_out, int out_size)
{
    (void)in_sizes; (void)n_in; (void)out_size;
    const float* x = (const float*)d_in[0];
    float* out = (float*)d_out;
    iqi3d_kernel<<<NBLOCKS, 128>>>(x, out);
}

// round 17
// speedup vs baseline: 1.1163x; 1.1163x over previous
#include <cuda_runtime.h>
#include <cstdint>

// Problem shape fixed by setup_inputs(): x = (2, 4, 8, 256, 256) float32.
#define DD   8
#define HH   256
#define WW   256
#define NBC  8
#define HWsz 65536
#define DHWs 524288                  // 2^19
#define HT   2                       // h-rows per block tile
#define NTIL (HH / HT)               // 128
#define NBLOCKS (NBC * 3 * NTIL)     // 3072; edge pairs emit d=0/7 (no copy path)

#define MAX_SHIFT 0.6f
#define BONUS     10.0f

__device__ __forceinline__ float2 f2max(float2 a, float2 b) {
    return make_float2(fmaxf(a.x, b.x), fmaxf(a.y, b.y));
}

__device__ __forceinline__ void cp_async16(unsigned int dst_smem, const void* src) {
    asm volatile("cp.async.cg.shared.global [%0], [%1], 16;"
                 :: "r"(dst_smem), "l"(src) : "memory");
}

// One Newton step. Returns 0 = moved, 1 = converged (valid), 2 = invalid.
__device__ __forceinline__ int quad_step(
    float c000, float pxm, float pxp, float pym, float pyp, float psm, float psp,
    float e011, float e01m, float e0m1, float e0mm,
    float e101, float e10m, float em01, float em0m,
    float e110, float e1m0, float em10, float emm0,
    int& dc, int& hc, int& wc,
    float& shx, float& shy, float& shs, float& gds)
{
    float gx = 0.5f * (pxp - pxm);
    float gy = 0.5f * (pyp - pym);
    float gs = 0.5f * (psp - psm);
    float dxx = pxp - 2.0f * c000 + pxm;
    float dyy = pyp - 2.0f * c000 + pym;
    float dss = psp - 2.0f * c000 + psm;
    float dxy = 0.25f * (e011 - e01m - e0m1 + e0mm);
    float dxs = 0.25f * (e101 - e10m - em01 + em0m);
    float dys = 0.25f * (e110 - e1m0 - em10 + emm0);

    float cf00 = dyy * dss - dys * dys;
    float cf01 = dxy * dss - dys * dxs;
    float cf02 = dxy * dys - dyy * dxs;
    float det  = dxx * cf00 - dxy * cf01 + dxs * cf02;
    if (!(fabsf(det) > 0.0f)) return 2;

    float r0 = -gx, r1 = -gy, r2 = -gs;
    float sx = (r0 * cf00 - dxy * (r1 * dss - dys * r2) + dxs * (r1 * dys - dyy * r2)) / det;
    float sy = (dxx * (r1 * dss - dys * r2) - r0 * cf01 + dxs * (dxy * r2 - r1 * dxs)) / det;
    float ss = (dxx * (dyy * r2 - r1 * dys) - dxy * (dxy * r2 - r1 * dxs) + r0 * cf02) / det;

    shx = sx; shy = sy; shs = ss;
    gds = gx * sx + gy * sy + gs * ss;

    int mvx = (sx > MAX_SHIFT) ? 1 : ((sx < -MAX_SHIFT) ? -1 : 0);
    int nw = wc + mvx;
    if (nw < 1 || nw > WW - 2) return 2;
    wc = nw;
    int mvy = (sy > MAX_SHIFT) ? 1 : ((sy < -MAX_SHIFT) ? -1 : 0);
    int nh = hc + mvy;
    if (nh < 1 || nh > HH - 2) return 2;
    hc = nh;
    int mvs = (ss > MAX_SHIFT) ? 1 : ((ss < -MAX_SHIFT) ? -1 : 0);
    int nd = dc + mvs;
    if (nd < 1 || nd > DD - 2) return 2;
    dc = nd;

    return ((mvx | mvy | mvs) == 0) ? 1 : 0;
}

__global__ __launch_bounds__(128, 9)
void iqi3d_kernel(const float* __restrict__ x, float* __restrict__ out)
{
    const int tid  = threadIdx.x;
    const int lane = tid & 31;
    const int blk  = blockIdx.x;

    const int t    = blk & (NTIL - 1);
    const int q    = blk >> 7;
    const int pair = q % 3;              // 0,1,2  -> masked d = 2p+1, 2p+2
    const int bc   = q / 3;
    const int h0   = t * HT;
    const int dlo  = 2 * pair + 1;
    const int w2   = tid << 1;

    const float* __restrict__ xb = x + (size_t)bc * DHWs;

    // smem: raw input tile [row h0-1..h0+2][plane 2p..2p+3][256 w] = 16 KB
    __shared__ __align__(16) float tilef[4 * 4 * WW];
    __shared__ float sfull[4][WW];       // [d1A, d1B, d2A, d2B]
    __shared__ unsigned short slist[512];
    __shared__ int scount;
    if (tid == 0) scount = 0;

    // ---- prologue: async-fill the whole tile (no register destinations) ----
    {
        const unsigned int tbase = (unsigned int)__cvta_generic_to_shared(tilef);
#pragma unroll
        for (int i = 0; i < 8; ++i) {
            const int ch  = i * 128 + tid;      // 0..1023 16B chunks
            const int rp  = ch >> 6;            // 0..15 (row*4 + plane)
            const int w16 = ch & 63;
            const int row = rp >> 2;            // 0..3
            const int pl  = rp & 3;
            int hrow = h0 - 1 + row;
            if (hrow < 0) hrow = 0;
            if (hrow > HH - 1) hrow = HH - 1;
            const float* src = xb + (2 * pair + pl) * HWsz + hrow * WW + (w16 << 2);
            cp_async16(tbase + (unsigned int)(((rp * WW) + (w16 << 2)) << 2), src);
        }
        asm volatile("cp.async.commit_group;" ::: "memory");
        asm volatile("cp.async.wait_group 0;" ::: "memory");
    }
    __syncthreads();

    // ---- compute per-column maxes for both rows from the tile ----
    float2 M1[4], M2[4];
    float2 c1a, c2a, c1b, c2b;           // center values (planes d1,d2) rows A,B
    float2 e1a, e2a, e1b, e2b;           // d-excluded maxes
    float2 p0a, p3a, p0b, p3b;           // raw planes 0,3 (edge-pair outputs)
#pragma unroll
    for (int rr = 0; rr < 4; ++rr) {
        float2 v0 = *(float2*)&tilef[(rr * 4 + 0) * WW + w2];
        float2 v1 = *(float2*)&tilef[(rr * 4 + 1) * WW + w2];
        float2 v2 = *(float2*)&tilef[(rr * 4 + 2) * WW + w2];
        float2 v3 = *(float2*)&tilef[(rr * 4 + 3) * WW + w2];
        M1[rr] = f2max(f2max(v0, v1), v2);
        M2[rr] = f2max(f2max(v1, v2), v3);
        if (rr == 1) {
            c1a = v1; c2a = v2;
            e1a = f2max(v0, v2); e2a = f2max(v1, v3);
            p0a = v0; p3a = v3;
        }
        if (rr == 2) {
            c1b = v1; c2b = v2;
            e1b = f2max(v0, v2); e2b = f2max(v1, v3);
            p0b = v0; p3b = v3;
        }
    }
    const float2 full1A = f2max(f2max(M1[0], M1[1]), M1[2]);
    const float2 full1B = f2max(f2max(M1[1], M1[2]), M1[3]);
    const float2 full2A = f2max(f2max(M2[0], M2[1]), M2[2]);
    const float2 full2B = f2max(f2max(M2[1], M2[2]), M2[3]);
    const float2 ex1A = f2max(f2max(M1[0], M1[2]), e1a);
    const float2 ex1B = f2max(f2max(M1[1], M1[3]), e1b);
    const float2 ex2A = f2max(f2max(M2[0], M2[2]), e2a);
    const float2 ex2B = f2max(f2max(M2[1], M2[3]), e2b);

    *(float2*)&sfull[0][w2] = full1A;
    *(float2*)&sfull[1][w2] = full1B;
    *(float2*)&sfull[2][w2] = full2A;
    *(float2*)&sfull[3][w2] = full2B;
    __syncthreads();

    int il = w2 - 1; if (il < 0) il = 0;
    int ir = w2 + 2; if (ir > WW - 1) ir = WW - 1;

    const bool hinA = (h0 >= 1) & (h0 <= HH - 2);
    const bool hinB = (h0 + 1 >= 1) & (h0 + 1 <= HH - 2);
    const bool win0 = (w2 >= 1), win1 = (w2 <= WW - 3);

    const bool m1Ax = hinA & win0 & (c1a.x > fmaxf(ex1A.x, fmaxf(sfull[0][il], full1A.y)));
    const bool m1Ay = hinA & win1 & (c1a.y > fmaxf(ex1A.y, fmaxf(full1A.x, sfull[0][ir])));
    const bool m1Bx = hinB & win0 & (c1b.x > fmaxf(ex1B.x, fmaxf(sfull[1][il], full1B.y)));
    const bool m1By = hinB & win1 & (c1b.y > fmaxf(ex1B.y, fmaxf(full1B.x, sfull[1][ir])));
    const bool m2Ax = hinA & win0 & (c2a.x > fmaxf(ex2A.x, fmaxf(sfull[2][il], full2A.y)));
    const bool m2Ay = hinA & win1 & (c2a.y > fmaxf(ex2A.y, fmaxf(full2A.x, sfull[2][ir])));
    const bool m2Bx = hinB & win0 & (c2b.x > fmaxf(ex2B.x, fmaxf(sfull[3][il], full2B.y)));
    const bool m2By = hinB & win1 & (c2b.y > fmaxf(ex2B.y, fmaxf(full2B.x, sfull[3][ir])));

    // warp-aggregated append: one atomic per warp
    {
        unsigned bl[8];
        bool mk[8] = { m1Ax, m1Ay, m1Bx, m1By, m2Ax, m2Ay, m2Bx, m2By };
        // code: bit11 = dj, bit8 = row, low bits = w
        const int codes[8] = {
            (0 << 8) | w2, (0 << 8) | (w2 + 1),
            (1 << 8) | w2, (1 << 8) | (w2 + 1),
            (1 << 11) | (0 << 8) | w2, (1 << 11) | (0 << 8) | (w2 + 1),
            (1 << 11) | (1 << 8) | w2, (1 << 11) | (1 << 8) | (w2 + 1) };
        unsigned any = 0;
#pragma unroll
        for (int j = 0; j < 8; ++j) { bl[j] = __ballot_sync(0xffffffffu, mk[j]); any |= bl[j]; }
        if (any) {
            int n = 0;
#pragma unroll
            for (int j = 0; j < 8; ++j) n += __popc(bl[j]);
            int leader = __ffs(any) - 1;
            int base;
            if (lane == leader) base = atomicAdd(&scount, n);
            base = __shfl_sync(0xffffffffu, base, leader);
            unsigned lt = (lane == 31) ? 0x7fffffffu : ((1u << lane) - 1u);
            int o = base;
#pragma unroll
            for (int j = 0; j < 8; ++j) {
                if (mk[j]) slist[o + __popc(bl[j] & lt)] = (unsigned short)codes[j];
                o += __popc(bl[j]);
            }
        }
    }

    // ---- default outputs for both rows ----
    float* __restrict__ obase = out + (size_t)bc * 3 * DHWs;
    float* __restrict__ ybase = out + (size_t)NBC * 3 * DHWs + (size_t)bc * DHWs;
    const float fw0 = (float)w2, fw1 = (float)(w2 + 1);
#pragma unroll
    for (int r = 0; r < 2; ++r) {
        const int h = h0 + r;
        const float fh = (float)h;
        const int hw = h * WW + w2;
        const float2 y1 = r ? c1b : c1a;
        const float2 y2 = r ? c2b : c2a;
        int off = dlo * HWsz + hw;
        *(float2*)&obase[off]            = make_float2((float)dlo, (float)dlo);
        *(float2*)&obase[DHWs + off]     = make_float2(fw0, fw1);
        *(float2*)&obase[2 * DHWs + off] = make_float2(fh, fh);
        *(float2*)&ybase[off]            = y1;
        off += HWsz;
        *(float2*)&obase[off]            = make_float2((float)(dlo + 1), (float)(dlo + 1));
        *(float2*)&obase[DHWs + off]     = make_float2(fw0, fw1);
        *(float2*)&obase[2 * DHWs + off] = make_float2(fh, fh);
        *(float2*)&ybase[off]            = y2;
        if (pair == 0) {
            const int o0 = hw;                        // d = 0
            *(float2*)&obase[o0]            = make_float2(0.f, 0.f);
            *(float2*)&obase[DHWs + o0]     = make_float2(fw0, fw1);
            *(float2*)&obase[2 * DHWs + o0] = make_float2(fh, fh);
            *(float2*)&ybase[o0]            = r ? p0b : p0a;
        } else if (pair == 2) {
            const int o7 = 7 * HWsz + hw;             // d = 7
            *(float2*)&obase[o7]            = make_float2(7.f, 7.f);
            *(float2*)&obase[DHWs + o7]     = make_float2(fw0, fw1);
            *(float2*)&obase[2 * DHWs + o7] = make_float2(fh, fh);
            *(float2*)&ybase[o7]            = r ? p3b : p3a;
        }
    }

    // =========== phase 2: refine; iteration 0 entirely from the smem tile ===========
    __syncthreads();
    const int cnt = scount;
#pragma unroll 1
    for (int i = tid; i < cnt; i += 128) {
        const int code = slist[i];
        const int dj = (code >> 11) & 1;
        const int r  = (code >> 8) & 1;
        const int w  = code & 255;
        const int d  = dlo + dj;
        const int h  = h0 + r;
        const int sp = d * HWsz + h * WW + w;

        int dc = d, hc = h, wc = w;
        float shx = 0.f, shy = 0.f, shs = 0.f, gds = 0.f;

        // iteration 0 at the original position: all 19 taps from smem.
        const int tb = (((r + 1) * 4) + (dj + 1)) * WW + w;
        #define TT(od, oh, ow) tilef[tb + (oh) * (4 * WW) + (od) * WW + (ow)]
        const float cen = TT(0, 0, 0);
        int st = quad_step(cen,
            TT(0, 0, -1), TT(0, 0, 1),
            TT(0, -1, 0), TT(0, 1, 0),
            TT(-1, 0, 0), TT(1, 0, 0),
            TT(0, 1, 1), TT(0, 1, -1), TT(0, -1, 1), TT(0, -1, -1),
            TT(1, 0, 1), TT(1, 0, -1), TT(-1, 0, 1), TT(-1, 0, -1),
            TT(1, 1, 0), TT(1, -1, 0), TT(-1, 1, 0), TT(-1, -1, 0),
            dc, hc, wc, shx, shy, shs, gds);
        #undef TT

        // iterations 1..4 at (possibly) moved positions: global path
#pragma unroll 1
        for (int itn = 1; (itn < 5) && (st == 0); ++itn) {
            int ds_ = min(max(dc, 1), DD - 2);
            int hs_ = min(max(hc, 1), HH - 2);
            int ws_ = min(max(wc, 1), WW - 2);
            const float* pp = xb + ds_ * HWsz + hs_ * WW + ws_;
            st = quad_step(pp[0],
                pp[-1], pp[1], pp[-WW], pp[WW], pp[-HWsz], pp[HWsz],
                pp[WW + 1], pp[WW - 1], pp[-WW + 1], pp[-WW - 1],
                pp[HWsz + 1], pp[HWsz - 1], pp[-HWsz + 1], pp[-HWsz - 1],
                pp[HWsz + WW], pp[HWsz - WW], pp[-HWsz + WW], pp[-HWsz - WW],
                dc, hc, wc, shx, shy, shs, gds);
        }

        bool valid = (st != 2)
                   && (fabsf(shx) <= 1.5f) && (fabsf(shy) <= 1.5f) && (fabsf(shs) <= 1.5f);
        if (valid) {
            const int cb = bc * 3 * DHWs;
            out[cb + 0 * DHWs + sp] = (float)dc + shs;
            out[cb + 1 * DHWs + sp] = (float)wc + shx;
            out[cb + 2 * DHWs + sp] = (float)hc + shy;
            out[(size_t)NBC * 3 * DHWs + (size_t)bc * DHWs + sp] =
                cen + (0.5f * gds + BONUS);
        }
    }
}

extern "C" void kernel_launch(void* const* d_in, const int* in_sizes, int n_in,
                              void* d_out, int out_size)
{
    (void)in_sizes; (void)n_in; (void)out_size;
    const float* x = (const float*)d_in[0];
    float* out = (float*)d_out;
    iqi3d_kernel<<<NBLOCKS, 128>>>(x, out);
}